// round 5
// baseline (speedup 1.0000x reference)
#include <cuda_runtime.h>
#include <cuda_bf16.h>
#include <math.h>
#include <stdint.h>

// Problem constants
#define B_  4
#define S_  1024
#define D_  1024
#define H_  16
#define BH  64     // B*H

// ---------------------------------------------------------------------------
// Scratch (static __device__ arrays). All "h/l" arrays hold packed bf16 pairs:
// word w = bf16(x[2w]) | bf16(x[2w+1])<<16, hi = rn(x), lo = rn(x - hi).
// ---------------------------------------------------------------------------
static __device__ uint32_t g_INh[(size_t)5 * 4096 * 512];   // [qa,qg,ka,kg,va] inputs
static __device__ uint32_t g_INl[(size_t)5 * 4096 * 512];
static __device__ uint32_t g_Wh[(size_t)4194304];           // Wqa..Wva,Wgate,Winfo
static __device__ uint32_t g_Wl[(size_t)4194304];
static __device__ uint32_t g_Qh[(size_t)BH * S_ * 64];      // [bh,s,64w] (qa|qg)
static __device__ uint32_t g_Ql[(size_t)BH * S_ * 64];
static __device__ uint32_t g_Kh[(size_t)BH * S_ * 64];
static __device__ uint32_t g_Kl[(size_t)BH * S_ * 64];
static __device__ float    g_V [(size_t)BH * 64 * S_];      // transposed [bh,j,s] fp32
static __device__ uint32_t g_Xh[(size_t)4096 * 512];        // attn out packed
static __device__ uint32_t g_Xl[(size_t)4096 * 512];
static __device__ float    g_G [(size_t)4096 * 1024];       // gate fp32

// Weight word offsets
#define OW_QA 0u
#define OW_QG 524288u
#define OW_KA 1048576u
#define OW_KG 1572864u
#define OW_VA 2097152u
#define OW_GATE 2621440u
#define OW_INFO 3670016u

// ---------------------------------------------------------------------------
__device__ __forceinline__ void cvt_split2(float x, float y, uint32_t &hi, uint32_t &lo) {
    __nv_bfloat16 hx = __float2bfloat16_rn(x);
    __nv_bfloat16 hy = __float2bfloat16_rn(y);
    float rx = x - __bfloat162float(hx);
    float ry = y - __bfloat162float(hy);
    __nv_bfloat16 lx = __float2bfloat16_rn(rx);
    __nv_bfloat16 ly = __float2bfloat16_rn(ry);
    hi = (uint32_t)__bfloat16_as_ushort(hx) | ((uint32_t)__bfloat16_as_ushort(hy) << 16);
    lo = (uint32_t)__bfloat16_as_ushort(lx) | ((uint32_t)__bfloat16_as_ushort(ly) << 16);
}

__device__ __forceinline__ void mma_bf16(float* c,
    uint32_t a0, uint32_t a1, uint32_t a2, uint32_t a3,
    uint32_t b0, uint32_t b1)
{
    asm volatile(
        "mma.sync.aligned.m16n8k16.row.col.f32.bf16.bf16.f32 "
        "{%0,%1,%2,%3},{%4,%5,%6,%7},{%8,%9},{%0,%1,%2,%3};"
        : "+f"(c[0]), "+f"(c[1]), "+f"(c[2]), "+f"(c[3])
        : "r"(a0), "r"(a1), "r"(a2), "r"(a3), "r"(b0), "r"(b1));
}

// ---------------------------------------------------------------------------
// Conversion kernels (once per launch)
// ---------------------------------------------------------------------------
__global__ __launch_bounds__(256) void conv_in_kernel(
    const float* __restrict__ q_g, const float* __restrict__ k_g,
    const float* __restrict__ q_a, const float* __restrict__ k_a,
    const float* __restrict__ v_a)
{
    const int z = blockIdx.y;
    const float* src = (z == 0) ? q_a : (z == 1) ? q_g : (z == 2) ? k_a
                     : (z == 3) ? k_g : v_a;
    const size_t i = (size_t)blockIdx.x * 256 + threadIdx.x;   // float4 idx, 1M/slice
    float4 v = ((const float4*)src)[i];
    uint32_t h0, l0, h1, l1;
    cvt_split2(v.x, v.y, h0, l0);
    cvt_split2(v.z, v.w, h1, l1);
    const size_t w = (size_t)z * 2097152 + i * 2;
    g_INh[w] = h0; g_INh[w + 1] = h1;
    g_INl[w] = l0; g_INl[w + 1] = l1;
}

__global__ __launch_bounds__(256) void conv_w_kernel(
    const float* __restrict__ Wqa, const float* __restrict__ Wqg,
    const float* __restrict__ Wka, const float* __restrict__ Wkg,
    const float* __restrict__ Wva, const float* __restrict__ Wgate,
    const float* __restrict__ Winfo)
{
    const int z = blockIdx.y;
    const float* src; size_t offw; size_t nf4;
    switch (z) {
        case 0: src = Wqa;   offw = OW_QA;   nf4 = 262144; break;
        case 1: src = Wqg;   offw = OW_QG;   nf4 = 262144; break;
        case 2: src = Wka;   offw = OW_KA;   nf4 = 262144; break;
        case 3: src = Wkg;   offw = OW_KG;   nf4 = 262144; break;
        case 4: src = Wva;   offw = OW_VA;   nf4 = 262144; break;
        case 5: src = Wgate; offw = OW_GATE; nf4 = 524288; break;
        default: src = Winfo; offw = OW_INFO; nf4 = 262144; break;
    }
    for (size_t i = (size_t)blockIdx.x * 256 + threadIdx.x; i < nf4; i += 262144) {
        float4 v = ((const float4*)src)[i];
        uint32_t h0, l0, h1, l1;
        cvt_split2(v.x, v.y, h0, l0);
        cvt_split2(v.z, v.w, h1, l1);
        const size_t w = offw + i * 2;
        g_Wh[w] = h0; g_Wh[w + 1] = h1;
        g_Wl[w] = l0; g_Wl[w + 1] = l1;
    }
}

// ---------------------------------------------------------------------------
// GEMM: C[128,128] = A * B^T on pre-split word arrays. K-tile = 16 words.
// Double-buffered smem, register prefetch, ONE sync per tile.
// Dynamic smem: 2 stages x 4 arrays x [128][20] words = 81920 B.
// ---------------------------------------------------------------------------
#define GSMEM 81920
typedef uint32_t (*SmT)[20];

struct GT { uint4 ah[2], al[2], bh[2], bl[2]; };

__device__ __forceinline__ void ld_tile(
    const uint32_t* __restrict__ Ahp, const uint32_t* __restrict__ Alp, int ldaw,
    const uint32_t* __restrict__ A2h, const uint32_t* __restrict__ A2l, int ld2w, int kspw,
    const uint32_t* __restrict__ Bhp, const uint32_t* __restrict__ Blp, int ldbw,
    int m0, int n0, int kw0, GT& t)
{
    const int tid = threadIdx.x;
    #pragma unroll
    for (int c = 0; c < 2; c++) {
        const int cid = tid + c * 256;
        const int row = cid >> 2, colw = (cid & 3) << 2;
        const int gw = kw0 + colw;
        const uint32_t *pah, *pal;
        if (gw >= kspw) {
            pah = A2h + (size_t)(m0 + row) * ld2w + (gw - kspw);
            pal = A2l + (size_t)(m0 + row) * ld2w + (gw - kspw);
        } else {
            pah = Ahp + (size_t)(m0 + row) * ldaw + gw;
            pal = Alp + (size_t)(m0 + row) * ldaw + gw;
        }
        t.ah[c] = *(const uint4*)pah;
        t.al[c] = *(const uint4*)pal;
        t.bh[c] = *(const uint4*)(Bhp + (size_t)(n0 + row) * ldbw + gw);
        t.bl[c] = *(const uint4*)(Blp + (size_t)(n0 + row) * ldbw + gw);
    }
}

__device__ __forceinline__ void st_tile(const GT& t, uint32_t* sm, int stage)
{
    SmT Ah = (SmT)(sm + stage * 10240);
    SmT Al = (SmT)(sm + stage * 10240 + 2560);
    SmT Bh = (SmT)(sm + stage * 10240 + 5120);
    SmT Bl = (SmT)(sm + stage * 10240 + 7680);
    const int tid = threadIdx.x;
    #pragma unroll
    for (int c = 0; c < 2; c++) {
        const int cid = tid + c * 256;
        const int row = cid >> 2, colw = (cid & 3) << 2;
        *(uint4*)&Ah[row][colw] = t.ah[c];
        *(uint4*)&Al[row][colw] = t.al[c];
        *(uint4*)&Bh[row][colw] = t.bh[c];
        *(uint4*)&Bl[row][colw] = t.bl[c];
    }
}

__device__ __forceinline__ void mma_stage(
    uint32_t* sm, int stage, int wm, int wn, int g, int t, float acc[2][8][4])
{
    SmT Ah = (SmT)(sm + stage * 10240);
    SmT Al = (SmT)(sm + stage * 10240 + 2560);
    SmT Bh = (SmT)(sm + stage * 10240 + 5120);
    SmT Bl = (SmT)(sm + stage * 10240 + 7680);
    #pragma unroll
    for (int kk = 0; kk < 2; kk++) {
        const int pc = kk * 8;
        uint32_t ah[2][4], al[2][4];
        #pragma unroll
        for (int mt = 0; mt < 2; mt++) {
            #pragma unroll
            for (int q = 0; q < 4; q++) {
                const int row = wm + mt * 16 + g + (q & 1) * 8;
                const int col = pc + t + (q >> 1) * 4;
                ah[mt][q] = Ah[row][col];
                al[mt][q] = Al[row][col];
            }
        }
        #pragma unroll
        for (int nf = 0; nf < 8; nf++) {
            const int rb = wn + nf * 8 + g;
            const uint32_t bh0 = Bh[rb][pc + t], bh1 = Bh[rb][pc + t + 4];
            const uint32_t bl0 = Bl[rb][pc + t], bl1 = Bl[rb][pc + t + 4];
            #pragma unroll
            for (int mt = 0; mt < 2; mt++) {
                mma_bf16(acc[mt][nf], ah[mt][0], ah[mt][1], ah[mt][2], ah[mt][3], bh0, bh1);
                mma_bf16(acc[mt][nf], ah[mt][0], ah[mt][1], ah[mt][2], ah[mt][3], bl0, bl1);
                mma_bf16(acc[mt][nf], al[mt][0], al[mt][1], al[mt][2], al[mt][3], bh0, bh1);
            }
        }
    }
}

__device__ __forceinline__ void gemm_body(
    const uint32_t* Ahp, const uint32_t* Alp, int ldaw,
    const uint32_t* A2h, const uint32_t* A2l, int ld2w, int kspw,
    const uint32_t* Bhp, const uint32_t* Blp, int ldbw,
    int Kw, int m0, int n0, float acc[2][8][4], uint32_t* sm)
{
    const int warp = threadIdx.x >> 5, lane = threadIdx.x & 31;
    const int wm = (warp & 3) * 32;
    const int wn = (warp >> 2) * 64;
    const int g  = lane >> 2;
    const int t  = lane & 3;
    const int nK = Kw >> 4;

    GT tr;
    ld_tile(Ahp, Alp, ldaw, A2h, A2l, ld2w, kspw, Bhp, Blp, ldbw, m0, n0, 0, tr);
    st_tile(tr, sm, 0);

    for (int kt = 0; kt < nK; kt++) {
        __syncthreads();
        if (kt + 1 < nK)
            ld_tile(Ahp, Alp, ldaw, A2h, A2l, ld2w, kspw, Bhp, Blp, ldbw,
                    m0, n0, (kt + 1) * 16, tr);
        mma_stage(sm, kt & 1, wm, wn, g, t, acc);
        if (kt + 1 < nK)
            st_tile(tr, sm, (kt + 1) & 1);
    }
}

// ---------------------------------------------------------------------------
// Kernel: 5 head projections. Writes Q/K packed hi/lo, V fp32 transposed.
// ---------------------------------------------------------------------------
__global__ __launch_bounds__(256, 2) void proj_kernel(
    const float* __restrict__ bqa, const float* __restrict__ bqg,
    const float* __restrict__ bka, const float* __restrict__ bkg,
    const float* __restrict__ bva)
{
    extern __shared__ uint32_t sm[];
    const int p = blockIdx.z;
    const uint32_t* Ahp = g_INh + (size_t)p * 2097152;
    const uint32_t* Alp = g_INl + (size_t)p * 2097152;
    const uint32_t woff = (p == 0) ? OW_QA : (p == 1) ? OW_QG : (p == 2) ? OW_KA
                        : (p == 3) ? OW_KG : OW_VA;
    const float* bias = (p == 0) ? bqa : (p == 1) ? bqg : (p == 2) ? bka
                      : (p == 3) ? bkg : bva;

    const int m0 = blockIdx.y * 128;
    const int n0 = blockIdx.x * 128;
    float acc[2][8][4] = {};
    gemm_body(Ahp, Alp, 512, nullptr, nullptr, 512, 1 << 30,
              g_Wh + woff, g_Wl + woff, 512, 512, m0, n0, acc, sm);

    const int lane = threadIdx.x & 31, warp = threadIdx.x >> 5;
    const int wm = (warp & 3) * 32, wn = (warp >> 2) * 64;
    const int g = lane >> 2, t = lane & 3;

    #pragma unroll
    for (int nf = 0; nf < 8; nf++) {
        const int n  = n0 + wn + nf * 8 + 2 * t;
        const int h  = n >> 6, jj = n & 63;
        const float bx = bias[n], by = bias[n + 1];
        #pragma unroll
        for (int mt = 0; mt < 2; mt++) {
            #pragma unroll
            for (int h2 = 0; h2 < 2; h2++) {
                const int m = m0 + wm + mt * 16 + g + h2 * 8;
                const int b = m >> 10, s = m & 1023;
                const size_t bhh = (size_t)(b * 16 + h);
                const float vx = acc[mt][nf][h2 * 2 + 0] + bx;
                const float vy = acc[mt][nf][h2 * 2 + 1] + by;
                if (p == 4) {
                    g_V[(bhh * 64 + jj)     * 1024 + s] = vx;
                    g_V[(bhh * 64 + jj + 1) * 1024 + s] = vy;
                } else {
                    uint32_t hw, lw;
                    cvt_split2(vx, vy, hw, lw);
                    const size_t widx = (bhh * 1024 + s) * 64 + ((p & 1) ? 32 : 0) + (jj >> 1);
                    if (p < 2) { g_Qh[widx] = hw; g_Ql[widx] = lw; }
                    else       { g_Kh[widx] = hw; g_Kl[widx] = lw; }
                }
            }
        }
    }
}

// ---------------------------------------------------------------------------
// Kernel: gate = sigmoid(concat(qa,qg) @ Wgate^T + bgate), Kw=1024 words
// ---------------------------------------------------------------------------
__global__ __launch_bounds__(256, 2) void gate_kernel(const float* __restrict__ bgate)
{
    extern __shared__ uint32_t sm[];
    const int m0 = blockIdx.y * 128;
    const int n0 = blockIdx.x * 128;
    float acc[2][8][4] = {};
    gemm_body(g_INh, g_INl, 512,                       // qa slice
              g_INh + 2097152, g_INl + 2097152, 512, 512,  // qg slice, split at word 512
              g_Wh + OW_GATE, g_Wl + OW_GATE, 1024,
              1024, m0, n0, acc, sm);

    const int lane = threadIdx.x & 31, warp = threadIdx.x >> 5;
    const int wm = (warp & 3) * 32, wn = (warp >> 2) * 64;
    const int g = lane >> 2, t = lane & 3;

    #pragma unroll
    for (int nf = 0; nf < 8; nf++) {
        const int n = n0 + wn + nf * 8 + 2 * t;
        const float bx = bgate[n], by = bgate[n + 1];
        #pragma unroll
        for (int mt = 0; mt < 2; mt++) {
            #pragma unroll
            for (int h2 = 0; h2 < 2; h2++) {
                const int m = m0 + wm + mt * 16 + g + h2 * 8;
                float2 v;
                v.x = 1.0f / (1.0f + __expf(-(acc[mt][nf][h2 * 2 + 0] + bx)));
                v.y = 1.0f / (1.0f + __expf(-(acc[mt][nf][h2 * 2 + 1] + by)));
                *(float2*)&g_G[(size_t)m * 1024 + n] = v;
            }
        }
    }
}

// ---------------------------------------------------------------------------
// Kernel: fused flash attention (pre-split Q/K; V fp32 + in-kernel split).
// ---------------------------------------------------------------------------
#define ATTN_SMEM 176128

__global__ __launch_bounds__(256) void attn_kernel(const int* __restrict__ mask)
{
    extern __shared__ char smem[];
    uint32_t (*Qh)[68] = (uint32_t(*)[68])(smem);
    uint32_t (*Ql)[68] = (uint32_t(*)[68])(smem + 34816);
    uint32_t (*Kh)[68] = (uint32_t(*)[68])(smem + 69632);
    uint32_t (*Kl)[68] = (uint32_t(*)[68])(smem + 104448);
    uint32_t (*Vh)[68] = (uint32_t(*)[68])(smem + 139264);
    uint32_t (*Vl)[68] = (uint32_t(*)[68])(smem + 156672);
    float* redmax = (float*)(smem + 174080);
    float* redsum = (float*)(smem + 175104);
    float* Osum   = (float*)(smem + 69632);   // reuse K region

    const int tid  = threadIdx.x;
    const int warp = tid >> 5, lane = tid & 31;
    const int wm = (warp & 3) * 32;
    const int wn = (warp >> 2);
    const int g  = lane >> 2;
    const int t  = lane & 3;

    const int bh = blockIdx.y;
    const int b  = bh >> 4, h = bh & 15;
    const int m0 = blockIdx.x * 128;

    const uint32_t* Qhg = g_Qh + ((size_t)bh << 16);
    const uint32_t* Qlg = g_Ql + ((size_t)bh << 16);
    const uint32_t* Khg = g_Kh + ((size_t)bh << 16);
    const uint32_t* Klg = g_Kl + ((size_t)bh << 16);
    const float*    Vg  = g_V  + ((size_t)bh << 16);

    const int lrow = tid >> 5;
    const int col4 = (tid & 31) * 4;
    const int pcw  = (tid & 31) * 2;

    // ---- load Q tile once (pre-split words) ----
    #pragma unroll
    for (int i = 0; i < 16; i++) {
        const int r = lrow + i * 8;
        const size_t base = (size_t)(m0 + r) * 64 + pcw;
        *(uint2*)&Qh[r][pcw] = *(const uint2*)(Qhg + base);
        *(uint2*)&Ql[r][pcw] = *(const uint2*)(Qlg + base);
    }

    float o[2][8][4] = {};
    float mrun[2][2] = {{-INFINITY, -INFINITY}, {-INFINITY, -INFINITY}};
    float lrun[2][2] = {};
    const float scale = 0.08838834764831845f;   // 1/sqrt(128)

    for (int nt = 0; nt < 8; nt++) {
        const int n0 = nt * 128;
        __syncthreads();

        #pragma unroll
        for (int i = 0; i < 16; i++) {
            const int r = lrow + i * 8;
            const size_t base = (size_t)(n0 + r) * 64 + pcw;
            *(uint2*)&Kh[r][pcw] = *(const uint2*)(Khg + base);
            *(uint2*)&Kl[r][pcw] = *(const uint2*)(Klg + base);
        }
        #pragma unroll
        for (int i = 0; i < 8; i++) {
            const int r = lrow + i * 8;
            float4 v = *(const float4*)(Vg + (size_t)r * 1024 + n0 + col4);
            uint32_t h0, l0, h1, l1;
            cvt_split2(v.x, v.y, h0, l0);
            cvt_split2(v.z, v.w, h1, l1);
            Vh[r][pcw] = h0; Vh[r][pcw + 1] = h1;
            Vl[r][pcw] = l0; Vl[r][pcw + 1] = l1;
        }
        __syncthreads();

        // ---- S = Q K^T ----
        float s[2][8][4] = {};
        #pragma unroll
        for (int ks = 0; ks < 8; ks++) {
            const int pc = ks * 8;
            uint32_t ah[2][4], al[2][4];
            #pragma unroll
            for (int mt = 0; mt < 2; mt++) {
                #pragma unroll
                for (int q = 0; q < 4; q++) {
                    const int row = wm + mt * 16 + g + (q & 1) * 8;
                    const int col = pc + t + (q >> 1) * 4;
                    ah[mt][q] = Qh[row][col];
                    al[mt][q] = Ql[row][col];
                }
            }
            #pragma unroll
            for (int nf = 0; nf < 8; nf++) {
                const int rb = wn * 64 + nf * 8 + g;
                const uint32_t bh0 = Kh[rb][pc + t], bh1 = Kh[rb][pc + t + 4];
                const uint32_t bl0 = Kl[rb][pc + t], bl1 = Kl[rb][pc + t + 4];
                #pragma unroll
                for (int mt = 0; mt < 2; mt++) {
                    mma_bf16(s[mt][nf], ah[mt][0], ah[mt][1], ah[mt][2], ah[mt][3], bh0, bh1);
                    mma_bf16(s[mt][nf], ah[mt][0], ah[mt][1], ah[mt][2], ah[mt][3], bl0, bl1);
                    mma_bf16(s[mt][nf], al[mt][0], al[mt][1], al[mt][2], al[mt][3], bh0, bh1);
                }
            }
        }

        // ---- scale + mask + row max ----
        float pm[2][2];
        #pragma unroll
        for (int mt = 0; mt < 2; mt++) {
            #pragma unroll
            for (int h2 = 0; h2 < 2; h2++) {
                const int rglob = m0 + wm + mt * 16 + g + h2 * 8;
                float mx = -INFINITY;
                #pragma unroll
                for (int nf = 0; nf < 8; nf++) {
                    const int ncol = n0 + wn * 64 + nf * 8 + 2 * t;
                    const int2 mk = *(const int2*)(mask + (((size_t)b << 20) + ((size_t)rglob << 10) + ncol));
                    float v0 = s[mt][nf][h2 * 2 + 0] * scale;
                    float v1 = s[mt][nf][h2 * 2 + 1] * scale;
                    if (mk.x == 0) v0 = -1e9f;
                    if (mk.y == 0) v1 = -1e9f;
                    s[mt][nf][h2 * 2 + 0] = v0;
                    s[mt][nf][h2 * 2 + 1] = v1;
                    mx = fmaxf(mx, fmaxf(v0, v1));
                }
                pm[mt][h2] = mx;
            }
        }
        #pragma unroll
        for (int mt = 0; mt < 2; mt++)
            #pragma unroll
            for (int h2 = 0; h2 < 2; h2++) {
                pm[mt][h2] = fmaxf(pm[mt][h2], __shfl_xor_sync(0xffffffffu, pm[mt][h2], 1));
                pm[mt][h2] = fmaxf(pm[mt][h2], __shfl_xor_sync(0xffffffffu, pm[mt][h2], 2));
            }
        if (t == 0) {
            #pragma unroll
            for (int mt = 0; mt < 2; mt++)
                #pragma unroll
                for (int h2 = 0; h2 < 2; h2++)
                    redmax[wn * 128 + wm + mt * 16 + g + h2 * 8] = pm[mt][h2];
        }
        __syncthreads();

        // ---- running stats, exponentiate, rescale O ----
        float alpha[2][2], psum[2][2];
        #pragma unroll
        for (int mt = 0; mt < 2; mt++) {
            #pragma unroll
            for (int h2 = 0; h2 < 2; h2++) {
                const int rl = wm + mt * 16 + g + h2 * 8;
                const float mtile = fmaxf(redmax[rl], redmax[128 + rl]);
                const float mnew  = fmaxf(mrun[mt][h2], mtile);
                alpha[mt][h2] = __expf(mrun[mt][h2] - mnew);
                mrun[mt][h2]  = mnew;
                float ps = 0.0f;
                #pragma unroll
                for (int nf = 0; nf < 8; nf++) {
                    float p0 = __expf(s[mt][nf][h2 * 2 + 0] - mnew);
                    float p1 = __expf(s[mt][nf][h2 * 2 + 1] - mnew);
                    s[mt][nf][h2 * 2 + 0] = p0;
                    s[mt][nf][h2 * 2 + 1] = p1;
                    ps += p0 + p1;
                }
                psum[mt][h2] = ps;
            }
        }
        #pragma unroll
        for (int mt = 0; mt < 2; mt++)
            #pragma unroll
            for (int nf = 0; nf < 8; nf++)
                #pragma unroll
                for (int e = 0; e < 4; e++)
                    o[mt][nf][e] *= alpha[mt][e >> 1];
        #pragma unroll
        for (int mt = 0; mt < 2; mt++)
            #pragma unroll
            for (int h2 = 0; h2 < 2; h2++) {
                psum[mt][h2] += __shfl_xor_sync(0xffffffffu, psum[mt][h2], 1);
                psum[mt][h2] += __shfl_xor_sync(0xffffffffu, psum[mt][h2], 2);
            }
        if (t == 0) {
            #pragma unroll
            for (int mt = 0; mt < 2; mt++)
                #pragma unroll
                for (int h2 = 0; h2 < 2; h2++)
                    redsum[wn * 128 + wm + mt * 16 + g + h2 * 8] = psum[mt][h2];
        }
        __syncthreads();
        #pragma unroll
        for (int mt = 0; mt < 2; mt++)
            #pragma unroll
            for (int h2 = 0; h2 < 2; h2++) {
                const int rl = wm + mt * 16 + g + h2 * 8;
                lrun[mt][h2] = lrun[mt][h2] * alpha[mt][h2] + redsum[rl] + redsum[128 + rl];
            }

        // ---- O += P V ----
        #pragma unroll
        for (int ks2 = 0; ks2 < 4; ks2++) {
            uint32_t ah[2][4], al[2][4];
            #pragma unroll
            for (int mt = 0; mt < 2; mt++) {
                cvt_split2(s[mt][2 * ks2][0],     s[mt][2 * ks2][1],     ah[mt][0], al[mt][0]);
                cvt_split2(s[mt][2 * ks2][2],     s[mt][2 * ks2][3],     ah[mt][1], al[mt][1]);
                cvt_split2(s[mt][2 * ks2 + 1][0], s[mt][2 * ks2 + 1][1], ah[mt][2], al[mt][2]);
                cvt_split2(s[mt][2 * ks2 + 1][2], s[mt][2 * ks2 + 1][3], ah[mt][3], al[mt][3]);
            }
            const int vcol = wn * 32 + ks2 * 8 + t;
            #pragma unroll
            for (int nf = 0; nf < 8; nf++) {
                const int rv = nf * 8 + g;
                const uint32_t bh0 = Vh[rv][vcol], bh1 = Vh[rv][vcol + 4];
                const uint32_t bl0 = Vl[rv][vcol], bl1 = Vl[rv][vcol + 4];
                #pragma unroll
                for (int mt = 0; mt < 2; mt++) {
                    mma_bf16(o[mt][nf], ah[mt][0], ah[mt][1], ah[mt][2], ah[mt][3], bh0, bh1);
                    mma_bf16(o[mt][nf], ah[mt][0], ah[mt][1], ah[mt][2], ah[mt][3], bl0, bl1);
                    mma_bf16(o[mt][nf], al[mt][0], al[mt][1], al[mt][2], al[mt][3], bh0, bh1);
                }
            }
        }
    }

    // ---- epilogue: combine partials, normalize, write packed X ----
    __syncthreads();
    if (wn == 1) {
        #pragma unroll
        for (int mt = 0; mt < 2; mt++)
            #pragma unroll
            for (int h2 = 0; h2 < 2; h2++) {
                const int rl = wm + mt * 16 + g + h2 * 8;
                #pragma unroll
                for (int nf = 0; nf < 8; nf++) {
                    float2 v;
                    v.x = o[mt][nf][h2 * 2 + 0];
                    v.y = o[mt][nf][h2 * 2 + 1];
                    *(float2*)&Osum[rl * 66 + nf * 8 + 2 * t] = v;
                }
            }
    }
    __syncthreads();
    if (wn == 0) {
        #pragma unroll
        for (int mt = 0; mt < 2; mt++)
            #pragma unroll
            for (int h2 = 0; h2 < 2; h2++) {
                const int rl = wm + mt * 16 + g + h2 * 8;
                const float inv = 1.0f / lrun[mt][h2];
                #pragma unroll
                for (int nf = 0; nf < 8; nf++) {
                    const int c = nf * 8 + 2 * t;
                    float2 p = *(float2*)&Osum[rl * 66 + c];
                    const float vx = (o[mt][nf][h2 * 2 + 0] + p.x) * inv;
                    const float vy = (o[mt][nf][h2 * 2 + 1] + p.y) * inv;
                    uint32_t hw, lw;
                    cvt_split2(vx, vy, hw, lw);
                    const size_t widx = (size_t)(b * 1024 + m0 + rl) * 512 + ((h * 64 + c) >> 1);
                    g_Xh[widx] = hw;
                    g_Xl[widx] = lw;
                }
            }
    }
}

// ---------------------------------------------------------------------------
// Kernel: out = gate * (X @ Winfo^T + binfo)
// ---------------------------------------------------------------------------
__global__ __launch_bounds__(256, 2) void info_kernel(
    const float* __restrict__ binfo, float* __restrict__ out)
{
    extern __shared__ uint32_t sm[];
    const int m0 = blockIdx.y * 128;
    const int n0 = blockIdx.x * 128;
    float acc[2][8][4] = {};
    gemm_body(g_Xh, g_Xl, 512, nullptr, nullptr, 512, 1 << 30,
              g_Wh + OW_INFO, g_Wl + OW_INFO, 512, 512, m0, n0, acc, sm);

    const int lane = threadIdx.x & 31, warp = threadIdx.x >> 5;
    const int wm = (warp & 3) * 32, wn = (warp >> 2) * 64;
    const int g = lane >> 2, t = lane & 3;

    #pragma unroll
    for (int nf = 0; nf < 8; nf++) {
        const int n = n0 + wn + nf * 8 + 2 * t;
        const float bx = binfo[n], by = binfo[n + 1];
        #pragma unroll
        for (int mt = 0; mt < 2; mt++) {
            #pragma unroll
            for (int h2 = 0; h2 < 2; h2++) {
                const int m = m0 + wm + mt * 16 + g + h2 * 8;
                const float2 gg = *(const float2*)&g_G[(size_t)m * 1024 + n];
                float2 v;
                v.x = gg.x * (acc[mt][nf][h2 * 2 + 0] + bx);
                v.y = gg.y * (acc[mt][nf][h2 * 2 + 1] + by);
                *(float2*)&out[(size_t)m * 1024 + n] = v;
            }
        }
    }
}

// ---------------------------------------------------------------------------
extern "C" void kernel_launch(void* const* d_in, const int* in_sizes, int n_in,
                              void* d_out, int out_size)
{
    (void)in_sizes; (void)n_in; (void)out_size;
    const float* query_g = (const float*)d_in[0];
    const float* key_g   = (const float*)d_in[1];
    const float* query_a = (const float*)d_in[2];
    const float* key_a   = (const float*)d_in[3];
    const float* value_a = (const float*)d_in[4];
    const int*   mask    = (const int*)  d_in[5];
    const float* Wqg = (const float*)d_in[6];  const float* bqg = (const float*)d_in[7];
    const float* Wkg = (const float*)d_in[8];  const float* bkg = (const float*)d_in[9];
    const float* Wqa = (const float*)d_in[10]; const float* bqa = (const float*)d_in[11];
    const float* Wka = (const float*)d_in[12]; const float* bka = (const float*)d_in[13];
    const float* Wva = (const float*)d_in[14]; const float* bva = (const float*)d_in[15];
    const float* Wgate = (const float*)d_in[16]; const float* bgate = (const float*)d_in[17];
    const float* Winfo = (const float*)d_in[18]; const float* binfo = (const float*)d_in[19];

    static int attr_set = 0;
    if (!attr_set) {
        cudaFuncSetAttribute(attn_kernel, cudaFuncAttributeMaxDynamicSharedMemorySize, ATTN_SMEM);
        cudaFuncSetAttribute(proj_kernel, cudaFuncAttributeMaxDynamicSharedMemorySize, GSMEM);
        cudaFuncSetAttribute(gate_kernel, cudaFuncAttributeMaxDynamicSharedMemorySize, GSMEM);
        cudaFuncSetAttribute(info_kernel, cudaFuncAttributeMaxDynamicSharedMemorySize, GSMEM);
        attr_set = 1;
    }

    dim3 blk(256);
    conv_in_kernel<<<dim3(4096, 5), blk>>>(query_g, key_g, query_a, key_a, value_a);
    conv_w_kernel<<<dim3(1024, 7), blk>>>(Wqa, Wqg, Wka, Wkg, Wva, Wgate, Winfo);
    proj_kernel<<<dim3(8, 32, 5), blk, GSMEM>>>(bqa, bqg, bka, bkg, bva);
    gate_kernel<<<dim3(8, 32, 1), blk, GSMEM>>>(bgate);
    attn_kernel<<<dim3(8, 64), blk, ATTN_SMEM>>>(mask);
    info_kernel<<<dim3(8, 32, 1), blk, GSMEM>>>(binfo, (float*)d_out);
}